// round 1
// baseline (speedup 1.0000x reference)
#include <cuda_runtime.h>
#include <cuda_bf16.h>
#include <math.h>
#include <stdint.h>

// ---------------------------------------------------------------------------
// Problem constants
// ---------------------------------------------------------------------------
constexpr int CB  = 2;        // batch
constexpr int CS  = 2048;     // seq
constexpr int CD  = 1024;     // model dim
constexpr int CH  = 16;       // heads
constexpr int CDK = 64;       // head dim
constexpr int CFF = 4096;     // ffn dim
constexpr int CN  = CB * CS;  // 4096 rows

// ---------------------------------------------------------------------------
// Scratch (static device allocations — no cudaMalloc allowed)
// ---------------------------------------------------------------------------
__device__ float g_h  [ (size_t)CN * CD ];
__device__ float g_q  [ (size_t)CN * CD ];
__device__ float g_k  [ (size_t)CN * CD ];
__device__ float g_v  [ (size_t)CN * CD ];
__device__ float g_o  [ (size_t)CN * CD ];
__device__ float g_x2 [ (size_t)CN * CD ];
__device__ float g_u  [ (size_t)CN * CFF ];
__device__ float g_g  [ (size_t)CN * CFF ];

// ---------------------------------------------------------------------------
// RMSNorm: one block per row, 256 threads, D=1024 (one float4 per thread)
// ---------------------------------------------------------------------------
__global__ void __launch_bounds__(256) rmsnorm_kernel(
    const float* __restrict__ x, const float* __restrict__ w, float* __restrict__ out)
{
    int row = blockIdx.x;
    int t = threadIdx.x;
    const float4 v = reinterpret_cast<const float4*>(x + (size_t)row * CD)[t];
    float ss = v.x*v.x + v.y*v.y + v.z*v.z + v.w*v.w;
    #pragma unroll
    for (int o = 16; o > 0; o >>= 1) ss += __shfl_xor_sync(0xffffffffu, ss, o);
    __shared__ float red[8];
    if ((t & 31) == 0) red[t >> 5] = ss;
    __syncthreads();
    float tot = red[0];
    #pragma unroll
    for (int i = 1; i < 8; ++i) tot += red[i];
    float inv = rsqrtf(tot * (1.0f / CD) + 1e-5f);
    const float4 wv = reinterpret_cast<const float4*>(w)[t];
    float4 o4;
    o4.x = v.x * inv * wv.x;
    o4.y = v.y * inv * wv.y;
    o4.z = v.z * inv * wv.z;
    o4.w = v.w * inv * wv.w;
    reinterpret_cast<float4*>(out + (size_t)row * CD)[t] = o4;
}

// ---------------------------------------------------------------------------
// RoPE (in-place on q and k). One thread per (b,s,h,freq) pair.
// ---------------------------------------------------------------------------
__global__ void rope_kernel(float* __restrict__ q, float* __restrict__ k)
{
    int idx = blockIdx.x * blockDim.x + threadIdx.x;
    const int total = CB * CS * CH * (CDK / 2);
    if (idx >= total) return;
    int i = idx & 31;                 // freq index 0..31
    int h = (idx >> 5) & 15;
    int s = (idx >> 9) & (CS - 1);
    int b = idx >> (9 + 11);
    // inv_freq = 10000^(-i/32) = exp(-i * ln(10000)/32)
    const float c0 = 0.28782313662425572f; // ln(10000)/32
    float inv_freq = expf(-(float)i * c0);
    float ang = (float)s * inv_freq;
    float c, sn;
    __sincosf(ang, &sn, &c);   // fast path; replaced below for accuracy
    sn = sinf(ang); c = cosf(ang);
    size_t base = ((size_t)(b * CS + s)) * CD + h * CDK + 2 * i;
    float qe = q[base], qo = q[base + 1];
    q[base]     = c * qe - sn * qo;
    q[base + 1] = sn * qe + c * qo;
    float ke = k[base], ko = k[base + 1];
    k[base]     = c * ke - sn * ko;
    k[base + 1] = sn * ke + c * ko;
}

// ---------------------------------------------------------------------------
// SiLU(u) * g  -> u   (in place), float4 vectorized
// ---------------------------------------------------------------------------
__global__ void silu_mul_kernel(float* __restrict__ u, const float* __restrict__ g, int n4)
{
    int i = blockIdx.x * blockDim.x + threadIdx.x;
    if (i >= n4) return;
    float4 uu = reinterpret_cast<float4*>(u)[i];
    float4 gg = reinterpret_cast<const float4*>(g)[i];
    uu.x = uu.x / (1.0f + expf(-uu.x)) * gg.x;
    uu.y = uu.y / (1.0f + expf(-uu.y)) * gg.y;
    uu.z = uu.z / (1.0f + expf(-uu.z)) * gg.z;
    uu.w = uu.w / (1.0f + expf(-uu.w)) * gg.w;
    reinterpret_cast<float4*>(u)[i] = uu;
}

// ---------------------------------------------------------------------------
// Tiled SGEMM, NT:  C[M,N] = A[M,K] * B[N,K]^T  (+ optional residual Res[M,N])
// BM=BN=128, BK=16, 256 threads, 8x8 per-thread microtile.
// Requires M%128==0, N%128==0, K%16==0 (true for all call sites).
// ---------------------------------------------------------------------------
__global__ void __launch_bounds__(256) sgemm_nt(
    const float* __restrict__ A, const float* __restrict__ Bm,
    const float* __restrict__ Res, float* __restrict__ C,
    int M, int N, int K)
{
    __shared__ float As[128][17];
    __shared__ float Bs[128][17];

    const int tid = threadIdx.x;
    const int tx = tid & 15;
    const int ty = tid >> 4;
    const int m0 = blockIdx.y * 128;
    const int n0 = blockIdx.x * 128;

    const float* Ag = A  + (size_t)m0 * K;
    const float* Bg = Bm + (size_t)n0 * K;

    float acc[8][8];
    #pragma unroll
    for (int i = 0; i < 8; ++i)
        #pragma unroll
        for (int j = 0; j < 8; ++j) acc[i][j] = 0.0f;

    for (int kt = 0; kt < K; kt += 16) {
        #pragma unroll
        for (int it = 0; it < 2; ++it) {
            int idx = tid + it * 256;
            int r = idx >> 2;
            int c = (idx & 3) << 2;
            float4 va = *reinterpret_cast<const float4*>(Ag + (size_t)r * K + kt + c);
            As[r][c + 0] = va.x; As[r][c + 1] = va.y;
            As[r][c + 2] = va.z; As[r][c + 3] = va.w;
            float4 vb = *reinterpret_cast<const float4*>(Bg + (size_t)r * K + kt + c);
            Bs[r][c + 0] = vb.x; Bs[r][c + 1] = vb.y;
            Bs[r][c + 2] = vb.z; Bs[r][c + 3] = vb.w;
        }
        __syncthreads();
        #pragma unroll
        for (int kk = 0; kk < 16; ++kk) {
            float a[8], b[8];
            #pragma unroll
            for (int i = 0; i < 4; ++i) {
                a[i]     = As[ty * 4 + i][kk];
                a[i + 4] = As[64 + ty * 4 + i][kk];
            }
            #pragma unroll
            for (int j = 0; j < 4; ++j) {
                b[j]     = Bs[tx * 4 + j][kk];
                b[j + 4] = Bs[64 + tx * 4 + j][kk];
            }
            #pragma unroll
            for (int i = 0; i < 8; ++i)
                #pragma unroll
                for (int j = 0; j < 8; ++j)
                    acc[i][j] = fmaf(a[i], b[j], acc[i][j]);
        }
        __syncthreads();
    }

    #pragma unroll
    for (int i = 0; i < 8; ++i) {
        int m = m0 + ((i < 4) ? (ty * 4 + i) : (64 + ty * 4 + i - 4));
        #pragma unroll
        for (int j = 0; j < 8; ++j) {
            int n = n0 + ((j < 4) ? (tx * 4 + j) : (64 + tx * 4 + j - 4));
            float cv = acc[i][j];
            if (Res) cv += Res[(size_t)m * N + n];
            C[(size_t)m * N + n] = cv;
        }
    }
}

// ---------------------------------------------------------------------------
// Flash attention, causal. One block per (q_tile=64 rows, b*h).
// 256 threads: (tx,ty) grid 16x16, 4x4 microtiles.
// Dynamic smem: Qs/Ks/Vs/Ps each 64x65 floats (66,560 B total).
// ---------------------------------------------------------------------------
__global__ void __launch_bounds__(256) flash_attn_kernel(
    const float* __restrict__ Q, const float* __restrict__ K,
    const float* __restrict__ V, float* __restrict__ O)
{
    extern __shared__ float sm[];
    float* Qs = sm;
    float* Ks = sm + 64 * 65;
    float* Vs = sm + 2 * 64 * 65;
    float* Ps = sm + 3 * 64 * 65;

    const int tid = threadIdx.x;
    const int tx = tid & 15;
    const int ty = tid >> 4;
    const int bh = blockIdx.y;
    const int b = bh >> 4;
    const int h = bh & 15;
    const int q0 = blockIdx.x << 6;

    const float* Qp = Q + (size_t)b * CS * CD + h * CDK;
    const float* Kp = K + (size_t)b * CS * CD + h * CDK;
    const float* Vp = V + (size_t)b * CS * CD + h * CDK;

    // Load Q tile [64][64]
    for (int t = tid; t < 64 * 16; t += 256) {
        int r = t >> 4;
        int c = (t & 15) << 2;
        float4 v4 = *reinterpret_cast<const float4*>(Qp + (size_t)(q0 + r) * CD + c);
        float* d = Qs + r * 65 + c;
        d[0] = v4.x; d[1] = v4.y; d[2] = v4.z; d[3] = v4.w;
    }

    float o_acc[4][4];
    float m_i[4], l_i[4];
    #pragma unroll
    for (int i = 0; i < 4; ++i) {
        m_i[i] = -INFINITY; l_i[i] = 0.0f;
        #pragma unroll
        for (int j = 0; j < 4; ++j) o_acc[i][j] = 0.0f;
    }

    for (int kv0 = 0; kv0 <= q0; kv0 += 64) {
        __syncthreads();   // protects Ks/Vs/Ps reuse + covers initial Q load
        for (int t = tid; t < 64 * 16; t += 256) {
            int r = t >> 4;
            int c = (t & 15) << 2;
            float4 k4 = *reinterpret_cast<const float4*>(Kp + (size_t)(kv0 + r) * CD + c);
            float* dk = Ks + r * 65 + c;
            dk[0] = k4.x; dk[1] = k4.y; dk[2] = k4.z; dk[3] = k4.w;
            float4 v4 = *reinterpret_cast<const float4*>(Vp + (size_t)(kv0 + r) * CD + c);
            float* dv = Vs + r * 65 + c;
            dv[0] = v4.x; dv[1] = v4.y; dv[2] = v4.z; dv[3] = v4.w;
        }
        __syncthreads();

        // S = Q * K^T  (4x4 per thread)
        float s[4][4];
        #pragma unroll
        for (int i = 0; i < 4; ++i)
            #pragma unroll
            for (int j = 0; j < 4; ++j) s[i][j] = 0.0f;

        #pragma unroll 4
        for (int kk = 0; kk < 64; ++kk) {
            float a[4], bb[4];
            #pragma unroll
            for (int i = 0; i < 4; ++i) a[i] = Qs[(ty * 4 + i) * 65 + kk];
            #pragma unroll
            for (int j = 0; j < 4; ++j) bb[j] = Ks[(tx * 4 + j) * 65 + kk];
            #pragma unroll
            for (int i = 0; i < 4; ++i)
                #pragma unroll
                for (int j = 0; j < 4; ++j)
                    s[i][j] = fmaf(a[i], bb[j], s[i][j]);
        }

        // scale + causal mask
        #pragma unroll
        for (int i = 0; i < 4; ++i) {
            int qg = q0 + ty * 4 + i;
            #pragma unroll
            for (int j = 0; j < 4; ++j) {
                int kg = kv0 + tx * 4 + j;
                s[i][j] = (kg <= qg) ? s[i][j] * 0.125f : -INFINITY;
            }
        }

        // Online softmax per row (row stats replicated across 16 tx lanes)
        #pragma unroll
        for (int i = 0; i < 4; ++i) {
            float mt = fmaxf(fmaxf(s[i][0], s[i][1]), fmaxf(s[i][2], s[i][3]));
            #pragma unroll
            for (int off = 8; off > 0; off >>= 1)
                mt = fmaxf(mt, __shfl_xor_sync(0xffffffffu, mt, off));
            float mn = fmaxf(m_i[i], mt);
            float p[4], ls = 0.0f;
            #pragma unroll
            for (int j = 0; j < 4; ++j) { p[j] = expf(s[i][j] - mn); ls += p[j]; }
            #pragma unroll
            for (int off = 8; off > 0; off >>= 1)
                ls += __shfl_xor_sync(0xffffffffu, ls, off);
            float alpha = expf(m_i[i] - mn);
            l_i[i] = l_i[i] * alpha + ls;
            m_i[i] = mn;
            #pragma unroll
            for (int j = 0; j < 4; ++j) o_acc[i][j] *= alpha;
            #pragma unroll
            for (int j = 0; j < 4; ++j)
                Ps[(ty * 4 + i) * 65 + tx * 4 + j] = p[j];
        }
        __syncthreads();

        // O += P * V
        #pragma unroll 4
        for (int kk = 0; kk < 64; ++kk) {
            float pv[4], vv[4];
            #pragma unroll
            for (int i = 0; i < 4; ++i) pv[i] = Ps[(ty * 4 + i) * 65 + kk];
            #pragma unroll
            for (int j = 0; j < 4; ++j) vv[j] = Vs[kk * 65 + tx * 4 + j];
            #pragma unroll
            for (int i = 0; i < 4; ++i)
                #pragma unroll
                for (int j = 0; j < 4; ++j)
                    o_acc[i][j] = fmaf(pv[i], vv[j], o_acc[i][j]);
        }
    }

    // Write O (layout [b, s, h*64 + d] == transpose-back in reference)
    #pragma unroll
    for (int i = 0; i < 4; ++i) {
        float invl = 1.0f / l_i[i];
        size_t rowbase = ((size_t)b * CS + q0 + ty * 4 + i) * CD + h * CDK;
        #pragma unroll
        for (int j = 0; j < 4; ++j)
            O[rowbase + tx * 4 + j] = o_acc[i][j] * invl;
    }
}

// ---------------------------------------------------------------------------
// Launch
// ---------------------------------------------------------------------------
extern "C" void kernel_launch(void* const* d_in, const int* in_sizes, int n_in,
                              void* d_out, int out_size)
{
    const float* x    = (const float*)d_in[0];
    const float* w_q  = (const float*)d_in[1];
    const float* w_k  = (const float*)d_in[2];
    const float* w_v  = (const float*)d_in[3];
    const float* w_o  = (const float*)d_in[4];
    const float* ln1w = (const float*)d_in[5];
    const float* ln2w = (const float*)d_in[6];
    const float* w1   = (const float*)d_in[7];
    const float* w2   = (const float*)d_in[8];
    const float* w3   = (const float*)d_in[9];
    float* out = (float*)d_out;

    float *h, *q, *k, *v, *o, *x2, *u, *g;
    cudaGetSymbolAddress((void**)&h,  g_h);
    cudaGetSymbolAddress((void**)&q,  g_q);
    cudaGetSymbolAddress((void**)&k,  g_k);
    cudaGetSymbolAddress((void**)&v,  g_v);
    cudaGetSymbolAddress((void**)&o,  g_o);
    cudaGetSymbolAddress((void**)&x2, g_x2);
    cudaGetSymbolAddress((void**)&u,  g_u);
    cudaGetSymbolAddress((void**)&g,  g_g);

    const int FLASH_SMEM = 4 * 64 * 65 * (int)sizeof(float);
    cudaFuncSetAttribute(flash_attn_kernel,
                         cudaFuncAttributeMaxDynamicSharedMemorySize, FLASH_SMEM);

    // 1) h = rmsnorm(x, ln1)
    rmsnorm_kernel<<<CN, 256>>>(x, ln1w, h);

    // 2) q,k,v = h @ W^T
    dim3 gqkv(CD / 128, CN / 128);
    sgemm_nt<<<gqkv, 256>>>(h, w_q, nullptr, q, CN, CD, CD);
    sgemm_nt<<<gqkv, 256>>>(h, w_k, nullptr, k, CN, CD, CD);
    sgemm_nt<<<gqkv, 256>>>(h, w_v, nullptr, v, CN, CD, CD);

    // 3) RoPE on q,k
    {
        int pairs = CB * CS * CH * (CDK / 2);
        rope_kernel<<<(pairs + 255) / 256, 256>>>(q, k);
    }

    // 4) o = attention(q,k,v)  (causal, flash)
    dim3 gattn(CS / 64, CB * CH);
    flash_attn_kernel<<<gattn, 256, FLASH_SMEM>>>(q, k, v, o);

    // 5) x2 = x + o @ w_o^T
    sgemm_nt<<<gqkv, 256>>>(o, w_o, x, x2, CN, CD, CD);

    // 6) h = rmsnorm(x2, ln2)
    rmsnorm_kernel<<<CN, 256>>>(x2, ln2w, h);

    // 7) u = h @ w1^T ; g = h @ w3^T
    dim3 gff(CFF / 128, CN / 128);
    sgemm_nt<<<gff, 256>>>(h, w1, nullptr, u, CN, CFF, CD);
    sgemm_nt<<<gff, 256>>>(h, w3, nullptr, g, CN, CFF, CD);

    // 8) u = silu(u) * g
    {
        int n4 = CN * CFF / 4;
        silu_mul_kernel<<<(n4 + 255) / 256, 256>>>(u, g, n4);
    }

    // 9) out = x2 + u @ w2^T
    dim3 gdown(CD / 128, CN / 128);
    sgemm_nt<<<gdown, 256>>>(u, w2, x2, out, CN, CD, CFF);
}

// round 2
// speedup vs baseline: 2.6005x; 2.6005x over previous
#include <cuda_runtime.h>
#include <cuda_bf16.h>
#include <math.h>
#include <stdint.h>

// ---------------------------------------------------------------------------
// Problem constants
// ---------------------------------------------------------------------------
constexpr int CB  = 2;        // batch
constexpr int CS  = 2048;     // seq
constexpr int CD  = 1024;     // model dim
constexpr int CH  = 16;       // heads
constexpr int CDK = 64;       // head dim
constexpr int CFF = 4096;     // ffn dim
constexpr int CN  = CB * CS;  // 4096 rows

// ---------------------------------------------------------------------------
// Scratch (static device allocations — no cudaMalloc allowed)
// ---------------------------------------------------------------------------
__device__ float g_h  [ (size_t)CN * CD ];
__device__ float g_q  [ (size_t)CN * CD ];
__device__ float g_k  [ (size_t)CN * CD ];
__device__ float g_v  [ (size_t)CN * CD ];
__device__ float g_o  [ (size_t)CN * CD ];
__device__ float g_x2 [ (size_t)CN * CD ];
__device__ float g_u  [ (size_t)CN * CFF ];
__device__ float g_g  [ (size_t)CN * CFF ];
// tf32-rounded weights
__device__ float g_wq [ (size_t)CD * CD ];
__device__ float g_wk [ (size_t)CD * CD ];
__device__ float g_wv [ (size_t)CD * CD ];
__device__ float g_wo [ (size_t)CD * CD ];
__device__ float g_w1 [ (size_t)CFF * CD ];
__device__ float g_w2 [ (size_t)CD * CFF ];
__device__ float g_w3 [ (size_t)CFF * CD ];

// ---------------------------------------------------------------------------
// Helpers
// ---------------------------------------------------------------------------
__device__ __forceinline__ float tf32_rn(float x) {
    uint32_t t;
    asm("cvt.rna.tf32.f32 %0, %1;" : "=r"(t) : "f"(x));
    return __uint_as_float(t);
}

#define MMA_TF32(d, a, b)                                                     \
    asm volatile(                                                             \
        "mma.sync.aligned.m16n8k8.row.col.f32.tf32.tf32.f32 "                 \
        "{%0,%1,%2,%3}, {%4,%5,%6,%7}, {%8,%9}, {%0,%1,%2,%3};\n"             \
        : "+f"((d)[0]), "+f"((d)[1]), "+f"((d)[2]), "+f"((d)[3])              \
        : "r"((a)[0]), "r"((a)[1]), "r"((a)[2]), "r"((a)[3]),                 \
          "r"((b)[0]), "r"((b)[1]))

__device__ __forceinline__ void cp_async16(uint32_t smem_dst, const void* gmem_src) {
    asm volatile("cp.async.cg.shared.global [%0], [%1], 16;\n"
                 :: "r"(smem_dst), "l"(gmem_src));
}

// ---------------------------------------------------------------------------
// tf32 rounding pre-pass for weights (float4 vectorized)
// ---------------------------------------------------------------------------
__global__ void cvt_tf32_kernel(const float4* __restrict__ in, float4* __restrict__ out, int n4)
{
    int i = blockIdx.x * blockDim.x + threadIdx.x;
    if (i >= n4) return;
    float4 v = in[i];
    v.x = tf32_rn(v.x); v.y = tf32_rn(v.y);
    v.z = tf32_rn(v.z); v.w = tf32_rn(v.w);
    out[i] = v;
}

// ---------------------------------------------------------------------------
// RMSNorm: one block per row, 256 threads, D=1024. Output tf32-rounded
// (it feeds only GEMMs).
// ---------------------------------------------------------------------------
__global__ void __launch_bounds__(256) rmsnorm_kernel(
    const float* __restrict__ x, const float* __restrict__ w, float* __restrict__ out)
{
    int row = blockIdx.x;
    int t = threadIdx.x;
    const float4 v = reinterpret_cast<const float4*>(x + (size_t)row * CD)[t];
    float ss = v.x*v.x + v.y*v.y + v.z*v.z + v.w*v.w;
    #pragma unroll
    for (int o = 16; o > 0; o >>= 1) ss += __shfl_xor_sync(0xffffffffu, ss, o);
    __shared__ float red[8];
    if ((t & 31) == 0) red[t >> 5] = ss;
    __syncthreads();
    float tot = red[0];
    #pragma unroll
    for (int i = 1; i < 8; ++i) tot += red[i];
    float inv = rsqrtf(tot * (1.0f / CD) + 1e-5f);
    const float4 wv = reinterpret_cast<const float4*>(w)[t];
    float4 o4;
    o4.x = tf32_rn(v.x * inv * wv.x);
    o4.y = tf32_rn(v.y * inv * wv.y);
    o4.z = tf32_rn(v.z * inv * wv.z);
    o4.w = tf32_rn(v.w * inv * wv.w);
    reinterpret_cast<float4*>(out + (size_t)row * CD)[t] = o4;
}

// ---------------------------------------------------------------------------
// RoPE (in-place on q and k). q/k feed attention (fp32) — keep full precision.
// ---------------------------------------------------------------------------
__global__ void rope_kernel(float* __restrict__ q, float* __restrict__ k)
{
    int idx = blockIdx.x * blockDim.x + threadIdx.x;
    const int total = CB * CS * CH * (CDK / 2);
    if (idx >= total) return;
    int i = idx & 31;
    int h = (idx >> 5) & 15;
    int s = (idx >> 9) & (CS - 1);
    int b = idx >> (9 + 11);
    const float c0 = 0.28782313662425572f; // ln(10000)/32
    float inv_freq = expf(-(float)i * c0);
    float ang = (float)s * inv_freq;
    float sn = sinf(ang), c = cosf(ang);
    size_t base = ((size_t)(b * CS + s)) * CD + h * CDK + 2 * i;
    float qe = q[base], qo = q[base + 1];
    q[base]     = c * qe - sn * qo;
    q[base + 1] = sn * qe + c * qo;
    float ke = k[base], ko = k[base + 1];
    k[base]     = c * ke - sn * ko;
    k[base + 1] = sn * ke + c * ko;
}

// ---------------------------------------------------------------------------
// SiLU(u) * g -> u (in place). Output tf32-rounded (feeds down-proj GEMM).
// ---------------------------------------------------------------------------
__global__ void silu_mul_kernel(float* __restrict__ u, const float* __restrict__ g, int n4)
{
    int i = blockIdx.x * blockDim.x + threadIdx.x;
    if (i >= n4) return;
    float4 uu = reinterpret_cast<float4*>(u)[i];
    float4 gg = reinterpret_cast<const float4*>(g)[i];
    uu.x = tf32_rn(uu.x / (1.0f + expf(-uu.x)) * gg.x);
    uu.y = tf32_rn(uu.y / (1.0f + expf(-uu.y)) * gg.y);
    uu.z = tf32_rn(uu.z / (1.0f + expf(-uu.z)) * gg.z);
    uu.w = tf32_rn(uu.w / (1.0f + expf(-uu.w)) * gg.w);
    reinterpret_cast<float4*>(u)[i] = uu;
}

// ---------------------------------------------------------------------------
// TF32 tensor-core GEMM, NT: C[M,N] = A[M,K] * B[N,K]^T (+ optional Res)
// BM=BN=128, BK=32, 256 threads (8 warps as 2x4), warp tile 64x32,
// m16n8k8 fragments (4x4 tiles per warp), cp.async double buffering.
// A and B must already be tf32-rounded. M%128==0, N%128==0, K%32==0.
// ---------------------------------------------------------------------------
constexpr int GBM = 128, GBN = 128, GBK = 32;
constexpr int GLD = GBK + 4;   // 36-float row stride: conflict-free frag LDS
constexpr int STAGE_FLOATS = (GBM + GBN) * GLD;

__global__ void __launch_bounds__(256, 2) gemm_tf32(
    const float* __restrict__ A, const float* __restrict__ B,
    const float* __restrict__ Res, float* __restrict__ C,
    int M, int N, int K)
{
    extern __shared__ float sm[];

    const int tid  = threadIdx.x;
    const int lane = tid & 31;
    const int warp = tid >> 5;
    const int g    = lane >> 2;   // group id (0..7)
    const int q    = lane & 3;    // thread in group (0..3)
    const int wm   = (warp >> 2) * 64;  // warp m offset in tile
    const int wn   = (warp & 3) * 32;   // warp n offset in tile

    const int m0 = blockIdx.y * GBM;
    const int n0 = blockIdx.x * GBN;

    // smem stage bases (in floats)
    float* stA[2] = { sm,                      sm + STAGE_FLOATS };
    float* stB[2] = { sm + GBM * GLD,          sm + STAGE_FLOATS + GBM * GLD };
    uint32_t smA[2], smB[2];
    #pragma unroll
    for (int s = 0; s < 2; ++s) {
        smA[s] = (uint32_t)__cvta_generic_to_shared(stA[s]);
        smB[s] = (uint32_t)__cvta_generic_to_shared(stB[s]);
    }

    // loader coords: 4 rows x 8 cols of float4 per 256 threads, x4 row-iters
    const int lr = tid >> 3;        // 0..31
    const int lc = (tid & 7) * 4;   // 0,4,...,28

    const int NT = K / GBK;

    float acc[4][4][4];
    #pragma unroll
    for (int mt = 0; mt < 4; ++mt)
        #pragma unroll
        for (int nt = 0; nt < 4; ++nt)
            #pragma unroll
            for (int e = 0; e < 4; ++e) acc[mt][nt][e] = 0.0f;

    auto issue_tile = [&](int kt, int s) {
        const float* Ag = A + (size_t)m0 * K + (size_t)kt * GBK;
        const float* Bg = B + (size_t)n0 * K + (size_t)kt * GBK;
        #pragma unroll
        for (int i = 0; i < 4; ++i) {
            int r = lr + i * 32;
            cp_async16(smA[s] + (uint32_t)((r * GLD + lc) * 4), Ag + (size_t)r * K + lc);
            cp_async16(smB[s] + (uint32_t)((r * GLD + lc) * 4), Bg + (size_t)r * K + lc);
        }
    };

    issue_tile(0, 0);
    asm volatile("cp.async.commit_group;\n" ::: "memory");

    for (int kt = 0; kt < NT; ++kt) {
        int cur = kt & 1;
        int nxt = cur ^ 1;
        if (kt + 1 < NT) issue_tile(kt + 1, nxt);
        asm volatile("cp.async.commit_group;\n" ::: "memory");
        asm volatile("cp.async.wait_group 1;\n" ::: "memory");
        __syncthreads();

        const float* As = stA[cur];
        const float* Bs = stB[cur];

        #pragma unroll
        for (int ks = 0; ks < 4; ++ks) {
            uint32_t afr[4][4], bfr[4][2];
            const int k0 = ks * 8;
            #pragma unroll
            for (int mt = 0; mt < 4; ++mt) {
                int r0 = wm + mt * 16 + g;
                afr[mt][0] = __float_as_uint(As[(r0    ) * GLD + k0 + q    ]);
                afr[mt][1] = __float_as_uint(As[(r0 + 8) * GLD + k0 + q    ]);
                afr[mt][2] = __float_as_uint(As[(r0    ) * GLD + k0 + q + 4]);
                afr[mt][3] = __float_as_uint(As[(r0 + 8) * GLD + k0 + q + 4]);
            }
            #pragma unroll
            for (int nt = 0; nt < 4; ++nt) {
                int r0 = wn + nt * 8 + g;
                bfr[nt][0] = __float_as_uint(Bs[r0 * GLD + k0 + q    ]);
                bfr[nt][1] = __float_as_uint(Bs[r0 * GLD + k0 + q + 4]);
            }
            #pragma unroll
            for (int mt = 0; mt < 4; ++mt)
                #pragma unroll
                for (int nt = 0; nt < 4; ++nt)
                    MMA_TF32(acc[mt][nt], afr[mt], bfr[nt]);
        }
        __syncthreads();
    }

    // Epilogue: c0,c1 -> (row, col..col+1), c2,c3 -> (row+8, col..col+1)
    #pragma unroll
    for (int mt = 0; mt < 4; ++mt) {
        int row0 = m0 + wm + mt * 16 + g;
        #pragma unroll
        for (int nt = 0; nt < 4; ++nt) {
            int col = n0 + wn + nt * 8 + q * 2;
            size_t i0 = (size_t)row0 * N + col;
            size_t i1 = (size_t)(row0 + 8) * N + col;
            float2 v0 = make_float2(acc[mt][nt][0], acc[mt][nt][1]);
            float2 v1 = make_float2(acc[mt][nt][2], acc[mt][nt][3]);
            if (Res) {
                float2 r0 = *reinterpret_cast<const float2*>(Res + i0);
                float2 r1 = *reinterpret_cast<const float2*>(Res + i1);
                v0.x += r0.x; v0.y += r0.y;
                v1.x += r1.x; v1.y += r1.y;
            }
            *reinterpret_cast<float2*>(C + i0) = v0;
            *reinterpret_cast<float2*>(C + i1) = v1;
        }
    }
}

// ---------------------------------------------------------------------------
// Flash attention, causal. One block per (q_tile=64 rows, b*h). fp32 FMA.
// Output tf32-rounded (feeds the O-projection GEMM only).
// ---------------------------------------------------------------------------
__global__ void __launch_bounds__(256) flash_attn_kernel(
    const float* __restrict__ Q, const float* __restrict__ K,
    const float* __restrict__ V, float* __restrict__ O)
{
    extern __shared__ float sm[];
    float* Qs = sm;
    float* Ks = sm + 64 * 65;
    float* Vs = sm + 2 * 64 * 65;
    float* Ps = sm + 3 * 64 * 65;

    const int tid = threadIdx.x;
    const int tx = tid & 15;
    const int ty = tid >> 4;
    const int bh = blockIdx.y;
    const int b = bh >> 4;
    const int h = bh & 15;
    const int q0 = blockIdx.x << 6;

    const float* Qp = Q + (size_t)b * CS * CD + h * CDK;
    const float* Kp = K + (size_t)b * CS * CD + h * CDK;
    const float* Vp = V + (size_t)b * CS * CD + h * CDK;

    for (int t = tid; t < 64 * 16; t += 256) {
        int r = t >> 4;
        int c = (t & 15) << 2;
        float4 v4 = *reinterpret_cast<const float4*>(Qp + (size_t)(q0 + r) * CD + c);
        float* d = Qs + r * 65 + c;
        d[0] = v4.x; d[1] = v4.y; d[2] = v4.z; d[3] = v4.w;
    }

    float o_acc[4][4];
    float m_i[4], l_i[4];
    #pragma unroll
    for (int i = 0; i < 4; ++i) {
        m_i[i] = -INFINITY; l_i[i] = 0.0f;
        #pragma unroll
        for (int j = 0; j < 4; ++j) o_acc[i][j] = 0.0f;
    }

    for (int kv0 = 0; kv0 <= q0; kv0 += 64) {
        __syncthreads();
        for (int t = tid; t < 64 * 16; t += 256) {
            int r = t >> 4;
            int c = (t & 15) << 2;
            float4 k4 = *reinterpret_cast<const float4*>(Kp + (size_t)(kv0 + r) * CD + c);
            float* dk = Ks + r * 65 + c;
            dk[0] = k4.x; dk[1] = k4.y; dk[2] = k4.z; dk[3] = k4.w;
            float4 v4 = *reinterpret_cast<const float4*>(Vp + (size_t)(kv0 + r) * CD + c);
            float* dv = Vs + r * 65 + c;
            dv[0] = v4.x; dv[1] = v4.y; dv[2] = v4.z; dv[3] = v4.w;
        }
        __syncthreads();

        float s[4][4];
        #pragma unroll
        for (int i = 0; i < 4; ++i)
            #pragma unroll
            for (int j = 0; j < 4; ++j) s[i][j] = 0.0f;

        #pragma unroll 4
        for (int kk = 0; kk < 64; ++kk) {
            float a[4], bb[4];
            #pragma unroll
            for (int i = 0; i < 4; ++i) a[i] = Qs[(ty * 4 + i) * 65 + kk];
            #pragma unroll
            for (int j = 0; j < 4; ++j) bb[j] = Ks[(tx * 4 + j) * 65 + kk];
            #pragma unroll
            for (int i = 0; i < 4; ++i)
                #pragma unroll
                for (int j = 0; j < 4; ++j)
                    s[i][j] = fmaf(a[i], bb[j], s[i][j]);
        }

        #pragma unroll
        for (int i = 0; i < 4; ++i) {
            int qg = q0 + ty * 4 + i;
            #pragma unroll
            for (int j = 0; j < 4; ++j) {
                int kg = kv0 + tx * 4 + j;
                s[i][j] = (kg <= qg) ? s[i][j] * 0.125f : -INFINITY;
            }
        }

        #pragma unroll
        for (int i = 0; i < 4; ++i) {
            float mt = fmaxf(fmaxf(s[i][0], s[i][1]), fmaxf(s[i][2], s[i][3]));
            #pragma unroll
            for (int off = 8; off > 0; off >>= 1)
                mt = fmaxf(mt, __shfl_xor_sync(0xffffffffu, mt, off));
            float mn = fmaxf(m_i[i], mt);
            float p[4], ls = 0.0f;
            #pragma unroll
            for (int j = 0; j < 4; ++j) { p[j] = expf(s[i][j] - mn); ls += p[j]; }
            #pragma unroll
            for (int off = 8; off > 0; off >>= 1)
                ls += __shfl_xor_sync(0xffffffffu, ls, off);
            float alpha = expf(m_i[i] - mn);
            l_i[i] = l_i[i] * alpha + ls;
            m_i[i] = mn;
            #pragma unroll
            for (int j = 0; j < 4; ++j) o_acc[i][j] *= alpha;
            #pragma unroll
            for (int j = 0; j < 4; ++j)
                Ps[(ty * 4 + i) * 65 + tx * 4 + j] = p[j];
        }
        __syncthreads();

        #pragma unroll 4
        for (int kk = 0; kk < 64; ++kk) {
            float pv[4], vv[4];
            #pragma unroll
            for (int i = 0; i < 4; ++i) pv[i] = Ps[(ty * 4 + i) * 65 + kk];
            #pragma unroll
            for (int j = 0; j < 4; ++j) vv[j] = Vs[kk * 65 + tx * 4 + j];
            #pragma unroll
            for (int i = 0; i < 4; ++i)
                #pragma unroll
                for (int j = 0; j < 4; ++j)
                    o_acc[i][j] = fmaf(pv[i], vv[j], o_acc[i][j]);
        }
    }

    #pragma unroll
    for (int i = 0; i < 4; ++i) {
        float invl = 1.0f / l_i[i];
        size_t rowbase = ((size_t)b * CS + q0 + ty * 4 + i) * CD + h * CDK;
        #pragma unroll
        for (int j = 0; j < 4; ++j)
            O[rowbase + tx * 4 + j] = tf32_rn(o_acc[i][j] * invl);
    }
}

// ---------------------------------------------------------------------------
// Launch
// ---------------------------------------------------------------------------
extern "C" void kernel_launch(void* const* d_in, const int* in_sizes, int n_in,
                              void* d_out, int out_size)
{
    const float* x    = (const float*)d_in[0];
    const float* w_q  = (const float*)d_in[1];
    const float* w_k  = (const float*)d_in[2];
    const float* w_v  = (const float*)d_in[3];
    const float* w_o  = (const float*)d_in[4];
    const float* ln1w = (const float*)d_in[5];
    const float* ln2w = (const float*)d_in[6];
    const float* w1   = (const float*)d_in[7];
    const float* w2   = (const float*)d_in[8];
    const float* w3   = (const float*)d_in[9];
    float* out = (float*)d_out;

    float *h, *q, *k, *v, *o, *x2, *u, *g;
    float *wq, *wk, *wv, *wo, *tw1, *tw2, *tw3;
    cudaGetSymbolAddress((void**)&h,  g_h);
    cudaGetSymbolAddress((void**)&q,  g_q);
    cudaGetSymbolAddress((void**)&k,  g_k);
    cudaGetSymbolAddress((void**)&v,  g_v);
    cudaGetSymbolAddress((void**)&o,  g_o);
    cudaGetSymbolAddress((void**)&x2, g_x2);
    cudaGetSymbolAddress((void**)&u,  g_u);
    cudaGetSymbolAddress((void**)&g,  g_g);
    cudaGetSymbolAddress((void**)&wq, g_wq);
    cudaGetSymbolAddress((void**)&wk, g_wk);
    cudaGetSymbolAddress((void**)&wv, g_wv);
    cudaGetSymbolAddress((void**)&wo, g_wo);
    cudaGetSymbolAddress((void**)&tw1, g_w1);
    cudaGetSymbolAddress((void**)&tw2, g_w2);
    cudaGetSymbolAddress((void**)&tw3, g_w3);

    const int FLASH_SMEM = 4 * 64 * 65 * (int)sizeof(float);
    const int GEMM_SMEM  = 2 * STAGE_FLOATS * (int)sizeof(float);
    cudaFuncSetAttribute(flash_attn_kernel,
                         cudaFuncAttributeMaxDynamicSharedMemorySize, FLASH_SMEM);
    cudaFuncSetAttribute(gemm_tf32,
                         cudaFuncAttributeMaxDynamicSharedMemorySize, GEMM_SMEM);

    // 0) tf32-round the weights
    {
        int n4a = CD * CD / 4;
        cvt_tf32_kernel<<<(n4a + 255) / 256, 256>>>((const float4*)w_q, (float4*)wq, n4a);
        cvt_tf32_kernel<<<(n4a + 255) / 256, 256>>>((const float4*)w_k, (float4*)wk, n4a);
        cvt_tf32_kernel<<<(n4a + 255) / 256, 256>>>((const float4*)w_v, (float4*)wv, n4a);
        cvt_tf32_kernel<<<(n4a + 255) / 256, 256>>>((const float4*)w_o, (float4*)wo, n4a);
        int n4b = CFF * CD / 4;
        cvt_tf32_kernel<<<(n4b + 255) / 256, 256>>>((const float4*)w1, (float4*)tw1, n4b);
        cvt_tf32_kernel<<<(n4b + 255) / 256, 256>>>((const float4*)w2, (float4*)tw2, n4b);
        cvt_tf32_kernel<<<(n4b + 255) / 256, 256>>>((const float4*)w3, (float4*)tw3, n4b);
    }

    // 1) h = rmsnorm(x, ln1)  (tf32-rounded output)
    rmsnorm_kernel<<<CN, 256>>>(x, ln1w, h);

    // 2) q,k,v = h @ W^T   (tensor cores)
    dim3 gqkv(CD / 128, CN / 128);
    gemm_tf32<<<gqkv, 256, GEMM_SMEM>>>(h, wq, nullptr, q, CN, CD, CD);
    gemm_tf32<<<gqkv, 256, GEMM_SMEM>>>(h, wk, nullptr, k, CN, CD, CD);
    gemm_tf32<<<gqkv, 256, GEMM_SMEM>>>(h, wv, nullptr, v, CN, CD, CD);

    // 3) RoPE on q,k
    {
        int pairs = CB * CS * CH * (CDK / 2);
        rope_kernel<<<(pairs + 255) / 256, 256>>>(q, k);
    }

    // 4) o = attention(q,k,v)  (causal, flash, fp32)
    dim3 gattn(CS / 64, CB * CH);
    flash_attn_kernel<<<gattn, 256, FLASH_SMEM>>>(q, k, v, o);

    // 5) x2 = x + o @ w_o^T
    gemm_tf32<<<gqkv, 256, GEMM_SMEM>>>(o, wo, x, x2, CN, CD, CD);

    // 6) h = rmsnorm(x2, ln2)
    rmsnorm_kernel<<<CN, 256>>>(x2, ln2w, h);

    // 7) u = h @ w1^T ; g = h @ w3^T
    dim3 gff(CFF / 128, CN / 128);
    gemm_tf32<<<gff, 256, GEMM_SMEM>>>(h, tw1, nullptr, u, CN, CFF, CD);
    gemm_tf32<<<gff, 256, GEMM_SMEM>>>(h, tw3, nullptr, g, CN, CFF, CD);

    // 8) u = silu(u) * g  (tf32-rounded output)
    {
        int n4 = CN * CFF / 4;
        silu_mul_kernel<<<(n4 + 255) / 256, 256>>>(u, g, n4);
    }

    // 9) out = x2 + u @ w2^T
    dim3 gdown(CD / 128, CN / 128);
    gemm_tf32<<<gdown, 256, GEMM_SMEM>>>(u, tw2, x2, out, CN, CD, CFF);
}

// round 5
// speedup vs baseline: 3.5302x; 1.3575x over previous
#include <cuda_runtime.h>
#include <cuda_bf16.h>
#include <math.h>
#include <stdint.h>

// ---------------------------------------------------------------------------
// Problem constants
// ---------------------------------------------------------------------------
constexpr int CB  = 2;
constexpr int CS  = 2048;
constexpr int CD  = 1024;
constexpr int CH  = 16;
constexpr int CDK = 64;
constexpr int CFF = 4096;
constexpr int CN  = CB * CS;

// ---------------------------------------------------------------------------
// Scratch (static device allocations)
// ---------------------------------------------------------------------------
__device__ float g_h   [ (size_t)CN * CD ];
__device__ float g_qkv [ (size_t)CN * 3 * CD ];
__device__ float g_o   [ (size_t)CN * CD ];
__device__ float g_x2  [ (size_t)CN * CD ];
__device__ float g_ug  [ (size_t)CN * 2 * CFF ];
__device__ float g_u   [ (size_t)CN * CFF ];
// tf32-rounded weights
__device__ float g_wqkv [ (size_t)3 * CD * CD ];
__device__ float g_wo   [ (size_t)CD * CD ];
__device__ float g_w13  [ (size_t)2 * CFF * CD ];
__device__ float g_w2   [ (size_t)CD * CFF ];

// ---------------------------------------------------------------------------
// Helpers
// ---------------------------------------------------------------------------
__device__ __forceinline__ float tf32_rn(float x) {
    uint32_t t;
    asm("cvt.rna.tf32.f32 %0, %1;" : "=r"(t) : "f"(x));
    return __uint_as_float(t);
}

#define MMA_TF32(d, a, b)                                                     \
    asm volatile(                                                             \
        "mma.sync.aligned.m16n8k8.row.col.f32.tf32.tf32.f32 "                 \
        "{%0,%1,%2,%3}, {%4,%5,%6,%7}, {%8,%9}, {%0,%1,%2,%3};\n"             \
        : "+f"((d)[0]), "+f"((d)[1]), "+f"((d)[2]), "+f"((d)[3])              \
        : "r"((a)[0]), "r"((a)[1]), "r"((a)[2]), "r"((a)[3]),                 \
          "r"((b)[0]), "r"((b)[1]))

__device__ __forceinline__ void cp_async16(uint32_t smem_dst, const void* gmem_src) {
    asm volatile("cp.async.cg.shared.global [%0], [%1], 16;\n"
                 :: "r"(smem_dst), "l"(gmem_src));
}

// ---------------------------------------------------------------------------
// tf32 rounding pre-pass for weights
// ---------------------------------------------------------------------------
__global__ void cvt_tf32_kernel(const float4* __restrict__ in, float4* __restrict__ out, int n4)
{
    int i = blockIdx.x * blockDim.x + threadIdx.x;
    if (i >= n4) return;
    float4 v = in[i];
    v.x = tf32_rn(v.x); v.y = tf32_rn(v.y);
    v.z = tf32_rn(v.z); v.w = tf32_rn(v.w);
    out[i] = v;
}

// ---------------------------------------------------------------------------
// RMSNorm (tf32-rounded output; feeds GEMMs only)
// ---------------------------------------------------------------------------
__global__ void __launch_bounds__(256) rmsnorm_kernel(
    const float* __restrict__ x, const float* __restrict__ w, float* __restrict__ out)
{
    int row = blockIdx.x;
    int t = threadIdx.x;
    const float4 v = reinterpret_cast<const float4*>(x + (size_t)row * CD)[t];
    float ss = v.x*v.x + v.y*v.y + v.z*v.z + v.w*v.w;
    #pragma unroll
    for (int o = 16; o > 0; o >>= 1) ss += __shfl_xor_sync(0xffffffffu, ss, o);
    __shared__ float red[8];
    if ((t & 31) == 0) red[t >> 5] = ss;
    __syncthreads();
    float tot = red[0];
    #pragma unroll
    for (int i = 1; i < 8; ++i) tot += red[i];
    float inv = rsqrtf(tot * (1.0f / CD) + 1e-5f);
    const float4 wv = reinterpret_cast<const float4*>(w)[t];
    float4 o4;
    o4.x = tf32_rn(v.x * inv * wv.x);
    o4.y = tf32_rn(v.y * inv * wv.y);
    o4.z = tf32_rn(v.z * inv * wv.z);
    o4.w = tf32_rn(v.w * inv * wv.w);
    reinterpret_cast<float4*>(out + (size_t)row * CD)[t] = o4;
}

// ---------------------------------------------------------------------------
// RoPE on merged qkv buffer [CN][3072]: q cols 0..1023, k cols 1024..2047.
// One thread per (b,s,h,freq-pair). Full fp32 (flash rounds on load).
// ---------------------------------------------------------------------------
__global__ void rope_kernel(float* __restrict__ qkv)
{
    int idx = blockIdx.x * blockDim.x + threadIdx.x;
    const int total = CB * CS * CH * (CDK / 2);
    if (idx >= total) return;
    int i = idx & 31;
    int h = (idx >> 5) & 15;
    int s = (idx >> 9) & (CS - 1);
    int b = idx >> 20;
    const float c0 = 0.28782313662425572f; // ln(10000)/32
    float inv_freq = expf(-(float)i * c0);
    float ang = (float)s * inv_freq;
    float sn = sinf(ang), c = cosf(ang);
    size_t base = ((size_t)(b * CS + s)) * 3072 + h * CDK + 2 * i;
    float qe = qkv[base], qo = qkv[base + 1];
    qkv[base]     = c * qe - sn * qo;
    qkv[base + 1] = sn * qe + c * qo;
    float ke = qkv[base + 1024], ko = qkv[base + 1025];
    qkv[base + 1024] = c * ke - sn * ko;
    qkv[base + 1025] = sn * ke + c * ko;
}

// ---------------------------------------------------------------------------
// SiLU(u)*g from merged [CN][2*CFF] buffer -> compact [CN][CFF], tf32-rounded
// ---------------------------------------------------------------------------
__global__ void silu_mul_kernel(const float* __restrict__ ug, float* __restrict__ u, int n4)
{
    int i = blockIdx.x * blockDim.x + threadIdx.x;
    if (i >= n4) return;
    int row = i >> 10;
    int c   = i & 1023;
    const float4* base = reinterpret_cast<const float4*>(ug) + (size_t)row * 2048;
    float4 uu = base[c];
    float4 gg = base[1024 + c];
    uu.x = tf32_rn(uu.x / (1.0f + expf(-uu.x)) * gg.x);
    uu.y = tf32_rn(uu.y / (1.0f + expf(-uu.y)) * gg.y);
    uu.z = tf32_rn(uu.z / (1.0f + expf(-uu.z)) * gg.z);
    uu.w = tf32_rn(uu.w / (1.0f + expf(-uu.w)) * gg.w);
    reinterpret_cast<float4*>(u)[i] = uu;
}

// ---------------------------------------------------------------------------
// TF32 tensor-core GEMM NT (round-2 proven, unchanged):
// C[M,N] = A[M,K]*B[N,K]^T (+Res)
// ---------------------------------------------------------------------------
constexpr int GBM = 128, GBN = 128, GBK = 32;
constexpr int GLD = GBK + 4;
constexpr int STAGE_FLOATS = (GBM + GBN) * GLD;

__global__ void __launch_bounds__(256, 2) gemm_tf32(
    const float* __restrict__ A, const float* __restrict__ B,
    const float* __restrict__ Res, float* __restrict__ C,
    int M, int N, int K)
{
    extern __shared__ float sm[];

    const int tid  = threadIdx.x;
    const int lane = tid & 31;
    const int warp = tid >> 5;
    const int g    = lane >> 2;
    const int q    = lane & 3;
    const int wm   = (warp >> 2) * 64;
    const int wn   = (warp & 3) * 32;

    const int m0 = blockIdx.y * GBM;
    const int n0 = blockIdx.x * GBN;

    float* stA[2] = { sm,             sm + STAGE_FLOATS };
    float* stB[2] = { sm + GBM * GLD, sm + STAGE_FLOATS + GBM * GLD };
    uint32_t smA[2], smB[2];
    #pragma unroll
    for (int s = 0; s < 2; ++s) {
        smA[s] = (uint32_t)__cvta_generic_to_shared(stA[s]);
        smB[s] = (uint32_t)__cvta_generic_to_shared(stB[s]);
    }

    const int lr = tid >> 3;
    const int lc = (tid & 7) * 4;
    const int NT = K / GBK;

    float acc[4][4][4];
    #pragma unroll
    for (int mt = 0; mt < 4; ++mt)
        #pragma unroll
        for (int nt = 0; nt < 4; ++nt)
            #pragma unroll
            for (int e = 0; e < 4; ++e) acc[mt][nt][e] = 0.0f;

    auto issue_tile = [&](int kt, int s) {
        const float* Ag = A + (size_t)m0 * K + (size_t)kt * GBK;
        const float* Bg = B + (size_t)n0 * K + (size_t)kt * GBK;
        #pragma unroll
        for (int i = 0; i < 4; ++i) {
            int r = lr + i * 32;
            cp_async16(smA[s] + (uint32_t)((r * GLD + lc) * 4), Ag + (size_t)r * K + lc);
            cp_async16(smB[s] + (uint32_t)((r * GLD + lc) * 4), Bg + (size_t)r * K + lc);
        }
    };

    issue_tile(0, 0);
    asm volatile("cp.async.commit_group;\n" ::: "memory");

    for (int kt = 0; kt < NT; ++kt) {
        int cur = kt & 1;
        int nxt = cur ^ 1;
        if (kt + 1 < NT) issue_tile(kt + 1, nxt);
        asm volatile("cp.async.commit_group;\n" ::: "memory");
        asm volatile("cp.async.wait_group 1;\n" ::: "memory");
        __syncthreads();

        const float* As = stA[cur];
        const float* Bs = stB[cur];

        #pragma unroll
        for (int ks = 0; ks < 4; ++ks) {
            uint32_t afr[4][4], bfr[4][2];
            const int k0 = ks * 8;
            #pragma unroll
            for (int mt = 0; mt < 4; ++mt) {
                int r0 = wm + mt * 16 + g;
                afr[mt][0] = __float_as_uint(As[(r0    ) * GLD + k0 + q    ]);
                afr[mt][1] = __float_as_uint(As[(r0 + 8) * GLD + k0 + q    ]);
                afr[mt][2] = __float_as_uint(As[(r0    ) * GLD + k0 + q + 4]);
                afr[mt][3] = __float_as_uint(As[(r0 + 8) * GLD + k0 + q + 4]);
            }
            #pragma unroll
            for (int nt = 0; nt < 4; ++nt) {
                int r0 = wn + nt * 8 + g;
                bfr[nt][0] = __float_as_uint(Bs[r0 * GLD + k0 + q    ]);
                bfr[nt][1] = __float_as_uint(Bs[r0 * GLD + k0 + q + 4]);
            }
            #pragma unroll
            for (int mt = 0; mt < 4; ++mt)
                #pragma unroll
                for (int nt = 0; nt < 4; ++nt)
                    MMA_TF32(acc[mt][nt], afr[mt], bfr[nt]);
        }
        __syncthreads();
    }

    #pragma unroll
    for (int mt = 0; mt < 4; ++mt) {
        int row0 = m0 + wm + mt * 16 + g;
        #pragma unroll
        for (int nt = 0; nt < 4; ++nt) {
            int col = n0 + wn + nt * 8 + q * 2;
            size_t i0 = (size_t)row0 * N + col;
            size_t i1 = (size_t)(row0 + 8) * N + col;
            float2 v0 = make_float2(acc[mt][nt][0], acc[mt][nt][1]);
            float2 v1 = make_float2(acc[mt][nt][2], acc[mt][nt][3]);
            if (Res) {
                float2 r0 = *reinterpret_cast<const float2*>(Res + i0);
                float2 r1 = *reinterpret_cast<const float2*>(Res + i1);
                v0.x += r0.x; v0.y += r0.y;
                v1.x += r1.x; v1.y += r1.y;
            }
            *reinterpret_cast<float2*>(C + i0) = v0;
            *reinterpret_cast<float2*>(C + i1) = v1;
        }
    }
}

// ---------------------------------------------------------------------------
// Tensor-core flash attention (causal, tf32 mma). ALL-FINITE arithmetic:
// mask value and m_i init are -1e30f (never +-INF), so no inf-inf paths.
// 128 q-rows per block, 8 warps x 16-row bands, kv tiles of 64, DK=64.
// ---------------------------------------------------------------------------
constexpr float NEG_BIG = -1e30f;
constexpr int AT_PAD = 68;
constexpr int FLASH_FLOATS = (128 + 64 + 64 + 128) * AT_PAD;

__global__ void __launch_bounds__(256) flash_tc(
    const float* __restrict__ QKV, float* __restrict__ O)
{
    extern __shared__ float sm[];
    float* Qs = sm;
    float* Ks = Qs + 128 * AT_PAD;
    float* Vs = Ks + 64 * AT_PAD;
    float* Ps = Vs + 64 * AT_PAD;

    const int tid  = threadIdx.x;
    const int lane = tid & 31;
    const int warp = tid >> 5;
    const int g = lane >> 2;
    const int q = lane & 3;
    const int wrow = warp * 16;

    const int bh = blockIdx.y;
    const int b = bh >> 4;
    const int h = bh & 15;
    const int q0 = blockIdx.x * 128;

    const float* Qp = QKV + (size_t)b * CS * 3072 + h * 64;
    const float* Kp = Qp + 1024;
    const float* Vp = Qp + 2048;

    for (int t = tid; t < 128 * 16; t += 256) {
        int r = t >> 4, c = (t & 15) << 2;
        float4 v4 = *reinterpret_cast<const float4*>(Qp + (size_t)(q0 + r) * 3072 + c);
        float* d = Qs + r * AT_PAD + c;
        d[0] = tf32_rn(v4.x); d[1] = tf32_rn(v4.y);
        d[2] = tf32_rn(v4.z); d[3] = tf32_rn(v4.w);
    }

    float o_acc[8][4];
    float m_i[2], l_i[2];
    #pragma unroll
    for (int r = 0; r < 2; ++r) { m_i[r] = NEG_BIG; l_i[r] = 0.0f; }
    #pragma unroll
    for (int nt = 0; nt < 8; ++nt)
        #pragma unroll
        for (int e = 0; e < 4; ++e) o_acc[nt][e] = 0.0f;

    const int ntiles = q0 / 64 + 2;
    for (int it = 0; it < ntiles; ++it) {
        const int kv0 = it * 64;
        __syncthreads();
        for (int t = tid; t < 64 * 16; t += 256) {
            int r = t >> 4, c = (t & 15) << 2;
            float4 k4 = *reinterpret_cast<const float4*>(Kp + (size_t)(kv0 + r) * 3072 + c);
            float* dk = Ks + r * AT_PAD + c;
            dk[0] = tf32_rn(k4.x); dk[1] = tf32_rn(k4.y);
            dk[2] = tf32_rn(k4.z); dk[3] = tf32_rn(k4.w);
            float4 v4 = *reinterpret_cast<const float4*>(Vp + (size_t)(kv0 + r) * 3072 + c);
            float* dv = Vs + r * AT_PAD + c;
            dv[0] = tf32_rn(v4.x); dv[1] = tf32_rn(v4.y);
            dv[2] = tf32_rn(v4.z); dv[3] = tf32_rn(v4.w);
        }
        __syncthreads();

        if (kv0 <= q0 + wrow + 15) {   // warp has at least one unmasked row
            // ---- S = Q K^T ----
            float s[8][4];
            #pragma unroll
            for (int nt = 0; nt < 8; ++nt)
                #pragma unroll
                for (int e = 0; e < 4; ++e) s[nt][e] = 0.0f;

            #pragma unroll
            for (int ks = 0; ks < 8; ++ks) {
                const int k0 = ks * 8;
                uint32_t a[4];
                a[0] = __float_as_uint(Qs[(wrow + g    ) * AT_PAD + k0 + q    ]);
                a[1] = __float_as_uint(Qs[(wrow + g + 8) * AT_PAD + k0 + q    ]);
                a[2] = __float_as_uint(Qs[(wrow + g    ) * AT_PAD + k0 + q + 4]);
                a[3] = __float_as_uint(Qs[(wrow + g + 8) * AT_PAD + k0 + q + 4]);
                #pragma unroll
                for (int nt = 0; nt < 8; ++nt) {
                    uint32_t bb[2];
                    bb[0] = __float_as_uint(Ks[(nt * 8 + g) * AT_PAD + k0 + q    ]);
                    bb[1] = __float_as_uint(Ks[(nt * 8 + g) * AT_PAD + k0 + q + 4]);
                    MMA_TF32(s[nt], a, bb);
                }
            }

            // scale + causal mask (finite mask value)
            const bool need_mask = (kv0 + 63 > q0 + wrow);
            #pragma unroll
            for (int nt = 0; nt < 8; ++nt)
                #pragma unroll
                for (int e = 0; e < 4; ++e) s[nt][e] *= 0.125f;
            if (need_mask) {
                #pragma unroll
                for (int nt = 0; nt < 8; ++nt) {
                    #pragma unroll
                    for (int e = 0; e < 4; ++e) {
                        int row = q0 + wrow + g + ((e >> 1) << 3);
                        int col = kv0 + nt * 8 + 2 * q + (e & 1);
                        if (col > row) s[nt][e] = NEG_BIG;
                    }
                }
            }

            // ---- online softmax (rows g and g+8) ----
            #pragma unroll
            for (int rh = 0; rh < 2; ++rh) {
                float mt = NEG_BIG;
                #pragma unroll
                for (int nt = 0; nt < 8; ++nt)
                    mt = fmaxf(mt, fmaxf(s[nt][2 * rh], s[nt][2 * rh + 1]));
                mt = fmaxf(mt, __shfl_xor_sync(0xffffffffu, mt, 1));
                mt = fmaxf(mt, __shfl_xor_sync(0xffffffffu, mt, 2));
                float mn = fmaxf(m_i[rh], mt);
                float ls = 0.0f;
                #pragma unroll
                for (int nt = 0; nt < 8; ++nt) {
                    float p0 = expf(s[nt][2 * rh    ] - mn);
                    float p1 = expf(s[nt][2 * rh + 1] - mn);
                    ls += p0 + p1;
                    s[nt][2 * rh    ] = p0;
                    s[nt][2 * rh + 1] = p1;
                }
                ls += __shfl_xor_sync(0xffffffffu, ls, 1);
                ls += __shfl_xor_sync(0xffffffffu, ls, 2);
                float alpha = expf(m_i[rh] - mn);
                l_i[rh] = l_i[rh] * alpha + ls;
                m_i[rh] = mn;
                #pragma unroll
                for (int nt = 0; nt < 8; ++nt) {
                    o_acc[nt][2 * rh    ] *= alpha;
                    o_acc[nt][2 * rh + 1] *= alpha;
                }
                float* prow = Ps + (wrow + g + 8 * rh) * AT_PAD;
                #pragma unroll
                for (int nt = 0; nt < 8; ++nt) {
                    prow[nt * 8 + 2 * q    ] = tf32_rn(s[nt][2 * rh    ]);
                    prow[nt * 8 + 2 * q + 1] = tf32_rn(s[nt][2 * rh + 1]);
                }
            }
            __syncwarp();

            // ---- O += P V ----
            #pragma unroll
            for (int ks = 0; ks < 8; ++ks) {
                const int k0 = ks * 8;
                uint32_t a[4];
                a[0] = __float_as_uint(Ps[(wrow + g    ) * AT_PAD + k0 + q    ]);
                a[1] = __float_as_uint(Ps[(wrow + g + 8) * AT_PAD + k0 + q    ]);
                a[2] = __float_as_uint(Ps[(wrow + g    ) * AT_PAD + k0 + q + 4]);
                a[3] = __float_as_uint(Ps[(wrow + g + 8) * AT_PAD + k0 + q + 4]);
                #pragma unroll
                for (int nt = 0; nt < 8; ++nt) {
                    uint32_t bb[2];
                    bb[0] = __float_as_uint(Vs[(k0 + q    ) * AT_PAD + nt * 8 + g]);
                    bb[1] = __float_as_uint(Vs[(k0 + q + 4) * AT_PAD + nt * 8 + g]);
                    MMA_TF32(o_acc[nt], a, bb);
                }
            }
        }
    }

    #pragma unroll
    for (int rh = 0; rh < 2; ++rh) {
        float invl = 1.0f / l_i[rh];
        int row = q0 + wrow + g + 8 * rh;
        size_t base = ((size_t)b * CS + row) * CD + h * 64;
        #pragma unroll
        for (int nt = 0; nt < 8; ++nt) {
            float2 v;
            v.x = tf32_rn(o_acc[nt][2 * rh    ] * invl);
            v.y = tf32_rn(o_acc[nt][2 * rh + 1] * invl);
            *reinterpret_cast<float2*>(&O[base + nt * 8 + 2 * q]) = v;
        }
    }
}

// ---------------------------------------------------------------------------
// Launch
// ---------------------------------------------------------------------------
extern "C" void kernel_launch(void* const* d_in, const int* in_sizes, int n_in,
                              void* d_out, int out_size)
{
    const float* x    = (const float*)d_in[0];
    const float* w_q  = (const float*)d_in[1];
    const float* w_k  = (const float*)d_in[2];
    const float* w_v  = (const float*)d_in[3];
    const float* w_o  = (const float*)d_in[4];
    const float* ln1w = (const float*)d_in[5];
    const float* ln2w = (const float*)d_in[6];
    const float* w1   = (const float*)d_in[7];
    const float* w2   = (const float*)d_in[8];
    const float* w3   = (const float*)d_in[9];
    float* out = (float*)d_out;

    float *h, *qkv, *o, *x2, *ug, *u;
    float *wqkv, *wo, *w13, *tw2;
    cudaGetSymbolAddress((void**)&h,    g_h);
    cudaGetSymbolAddress((void**)&qkv,  g_qkv);
    cudaGetSymbolAddress((void**)&o,    g_o);
    cudaGetSymbolAddress((void**)&x2,   g_x2);
    cudaGetSymbolAddress((void**)&ug,   g_ug);
    cudaGetSymbolAddress((void**)&u,    g_u);
    cudaGetSymbolAddress((void**)&wqkv, g_wqkv);
    cudaGetSymbolAddress((void**)&wo,   g_wo);
    cudaGetSymbolAddress((void**)&w13,  g_w13);
    cudaGetSymbolAddress((void**)&tw2,  g_w2);

    const int FLASH_SMEM = FLASH_FLOATS * (int)sizeof(float);
    const int GEMM_SMEM  = 2 * STAGE_FLOATS * (int)sizeof(float);
    cudaFuncSetAttribute(flash_tc,
                         cudaFuncAttributeMaxDynamicSharedMemorySize, FLASH_SMEM);
    cudaFuncSetAttribute(gemm_tf32,
                         cudaFuncAttributeMaxDynamicSharedMemorySize, GEMM_SMEM);

    // 0) tf32-round weights into merged buffers
    {
        int n4a = CD * CD / 4;
        cvt_tf32_kernel<<<(n4a + 255) / 256, 256>>>((const float4*)w_q, (float4*)(wqkv), n4a);
        cvt_tf32_kernel<<<(n4a + 255) / 256, 256>>>((const float4*)w_k, (float4*)(wqkv + (size_t)CD * CD), n4a);
        cvt_tf32_kernel<<<(n4a + 255) / 256, 256>>>((const float4*)w_v, (float4*)(wqkv + (size_t)2 * CD * CD), n4a);
        cvt_tf32_kernel<<<(n4a + 255) / 256, 256>>>((const float4*)w_o, (float4*)wo, n4a);
        int n4b = CFF * CD / 4;
        cvt_tf32_kernel<<<(n4b + 255) / 256, 256>>>((const float4*)w1, (float4*)(w13), n4b);
        cvt_tf32_kernel<<<(n4b + 255) / 256, 256>>>((const float4*)w3, (float4*)(w13 + (size_t)CFF * CD), n4b);
        cvt_tf32_kernel<<<(n4b + 255) / 256, 256>>>((const float4*)w2, (float4*)tw2, n4b);
    }

    // 1) h = rmsnorm(x, ln1)
    rmsnorm_kernel<<<CN, 256>>>(x, ln1w, h);

    // 2) qkv = h @ Wqkv^T
    {
        dim3 grid(3 * CD / 128, CN / 128);
        gemm_tf32<<<grid, 256, GEMM_SMEM>>>(h, wqkv, nullptr, qkv, CN, 3 * CD, CD);
    }

    // 3) RoPE on q,k columns of merged qkv
    {
        int pairs = CB * CS * CH * (CDK / 2);
        rope_kernel<<<(pairs + 255) / 256, 256>>>(qkv);
    }

    // 4) o = flash_attention(qkv)
    {
        dim3 grid(CS / 128, CB * CH);
        flash_tc<<<grid, 256, FLASH_SMEM>>>(qkv, o);
    }

    // 5) x2 = x + o @ w_o^T
    {
        dim3 grid(CD / 128, CN / 128);
        gemm_tf32<<<grid, 256, GEMM_SMEM>>>(o, wo, x, x2, CN, CD, CD);
    }

    // 6) h = rmsnorm(x2, ln2)
    rmsnorm_kernel<<<CN, 256>>>(x2, ln2w, h);

    // 7) ug = h @ [w1;w3]^T
    {
        dim3 grid(2 * CFF / 128, CN / 128);
        gemm_tf32<<<grid, 256, GEMM_SMEM>>>(h, w13, nullptr, ug, CN, 2 * CFF, CD);
    }

    // 8) u = silu(u)*g
    {
        int n4 = CN * CFF / 4;
        silu_mul_kernel<<<(n4 + 255) / 256, 256>>>(ug, u, n4);
    }

    // 9) out = x2 + u @ w2^T
    {
        dim3 grid(CD / 128, CN / 128);
        gemm_tf32<<<grid, 256, GEMM_SMEM>>>(u, tw2, x2, out, CN, CD, CFF);
    }
}